// round 7
// baseline (speedup 1.0000x reference)
#include <cuda_runtime.h>
#include <cuda_fp16.h>

#define ENT_DIM   288
#define REL_R     256
#define RTYPE_DIM 32
#define ROLE_DIM  256
#define N_TRIG    50000
#define N_ARGS    250000
#define ARG_DIM   576
#define OUT_DIM   544
#define NKEY      (2 * N_TRIG)
#define NSCANBLK  ((NKEY + 1023) / 1024)     // 98

#define BM 128
#define BN 256
#define BK 32
#define NKSTEP 18              // 576 / 32
#define BSTAGE 3
#define AS_STRIDE 40           // 32 + 8 pad (conflict-free ldmatrix)
#define BS_STRIDE 264          // 256 + 8 pad
#define GTHREADS 256
#define EP_STRIDE 132          // epilogue fp32 stage stride (mult of 4)
// mainloop: A 2*128*40*2 = 20480 B, B 3*32*264*2 = 50688 B -> 71168
// epilogue: 128*132*4 = 67584 B
#define SMEM_BYTES 71168

// -------- device scratch (no allocation allowed) --------
__device__ __half d_Wh[2 * ARG_DIM * ROLE_DIM];   // [g][k][n], g=0 -> W_in
__device__ int    d_perm[2 * N_ARGS];
__device__ int    d_keycnt[NKEY];
__device__ int    d_keyoff[NKEY];
__device__ int    d_blocksum[NSCANBLK];
__device__ int    d_blockoff[NSCANBLK];
__device__ int    d_gsplit;                        // #args in group 0

// -------- prep kernels --------
__global__ void zero_keys_kernel() {
    int i = blockIdx.x * blockDim.x + threadIdx.x;
    if (i < NKEY) d_keycnt[i] = 0;
}

__global__ void count_kernel(const int* __restrict__ arg_is_in,
                             const int* __restrict__ arg_trig) {
    int i = blockIdx.x * blockDim.x + threadIdx.x;
    if (i >= N_ARGS) return;
    int g = 1 - arg_is_in[i];
    atomicAdd(&d_keycnt[g * N_TRIG + arg_trig[i]], 1);
}

// ---- hierarchical exclusive scan over d_keycnt -> d_keyoff ----
__global__ void scan_blocks_kernel() {
    __shared__ int wsum[32];
    int b = blockIdx.x, tid = threadIdx.x;
    int k = b * 1024 + tid;
    int c = (k < NKEY) ? d_keycnt[k] : 0;
    int v = c;
    #pragma unroll
    for (int d = 1; d < 32; d <<= 1) {
        int t = __shfl_up_sync(0xffffffffu, v, d);
        if ((tid & 31) >= d) v += t;
    }
    if ((tid & 31) == 31) wsum[tid >> 5] = v;
    __syncthreads();
    if (tid < 32) {
        int w = wsum[tid];
        #pragma unroll
        for (int d = 1; d < 32; d <<= 1) {
            int t = __shfl_up_sync(0xffffffffu, w, d);
            if (tid >= d) w += t;
        }
        wsum[tid] = w;
    }
    __syncthreads();
    int base = (tid >= 32) ? wsum[(tid >> 5) - 1] : 0;
    int incl = v + base;
    if (k < NKEY) d_keyoff[k] = incl - c;          // block-local exclusive
    if (tid == 1023) d_blocksum[b] = incl;
}

__global__ void scan_top_kernel() {
    __shared__ int wsum[4];
    int tid = threadIdx.x;                          // 128 threads
    int c = (tid < NSCANBLK) ? d_blocksum[tid] : 0;
    int v = c;
    #pragma unroll
    for (int d = 1; d < 32; d <<= 1) {
        int t = __shfl_up_sync(0xffffffffu, v, d);
        if ((tid & 31) >= d) v += t;
    }
    if ((tid & 31) == 31) wsum[tid >> 5] = v;
    __syncthreads();
    if (tid < 4) {
        int w = wsum[tid];
        #pragma unroll
        for (int d = 1; d < 4; d <<= 1) {
            int t = __shfl_up_sync(0x0000000fu, w, d);
            if (tid >= d) w += t;
        }
        wsum[tid] = w;
    }
    __syncthreads();
    int base = (tid >= 32) ? wsum[(tid >> 5) - 1] : 0;
    if (tid < NSCANBLK) d_blockoff[tid] = v + base - c;
}

__global__ void scan_add_kernel() {
    int b = blockIdx.x, tid = threadIdx.x;
    int k = b * 1024 + tid;
    if (k < NKEY) {
        int off = d_keyoff[k] + d_blockoff[b];
        d_keyoff[k] = off;
        if (k == N_TRIG) d_gsplit = off;
    }
}

__global__ void scatter_kernel(const int* __restrict__ arg_is_in,
                               const int* __restrict__ arg_trig) {
    int i = blockIdx.x * blockDim.x + threadIdx.x;
    if (i >= N_ARGS) return;
    int g = 1 - arg_is_in[i];
    int key = g * N_TRIG + arg_trig[i];
    int pos = atomicAdd(&d_keyoff[key], 1);
    int local = pos - (g ? d_gsplit : 0);
    d_perm[g * N_ARGS + local] = i;
}

__global__ void convw_kernel(const float* __restrict__ W_in,
                             const float* __restrict__ W_out) {
    int i = blockIdx.x * blockDim.x + threadIdx.x;
    if (i >= 2 * ARG_DIM * ROLE_DIM) return;
    float v = (i < ARG_DIM * ROLE_DIM) ? W_in[i] : W_out[i - ARG_DIM * ROLE_DIM];
    d_Wh[i] = __float2half(v);
}

// out[t][0:288] = ent_embeds[trig_ent_id[t]], out[t][288:544] = 0
__global__ void init_out_kernel(const float* __restrict__ ent,
                                const int* __restrict__ trig_ent_id,
                                float* __restrict__ out) {
    int t = blockIdx.x * 4 + threadIdx.y;
    int c = threadIdx.x;                  // 0..135 (float4 units)
    if (t >= N_TRIG) return;
    float4 v;
    if (c < ENT_DIM / 4) {
        v = reinterpret_cast<const float4*>(ent)[(size_t)trig_ent_id[t] * (ENT_DIM / 4) + c];
    } else {
        v = make_float4(0.f, 0.f, 0.f, 0.f);
    }
    reinterpret_cast<float4*>(out)[(size_t)t * (OUT_DIM / 4) + c] = v;
}

// -------- main GEMM: y = x @ W_g, x gathered/concatenated on the fly --------
// 8 warps, warp grid 2(M) x 4(N), warp tile 64x64 (acc 128 fp32 / thread)
__global__ void __launch_bounds__(GTHREADS, 1)
gemm_kernel(const float* __restrict__ ent,
            const float* __restrict__ rel,
            const float* __restrict__ rtype,
            const int*   __restrict__ rtype_ids,
            const int*   __restrict__ arg_trig,
            const int*   __restrict__ arg_rel,
            const int*   __restrict__ arg_ent,
            float*       __restrict__ out) {
    extern __shared__ __half smem[];
    __half* As = smem;                          // [2][BM][AS_STRIDE]
    __half* Bs = smem + 2 * BM * AS_STRIDE;     // [BSTAGE][BK][BS_STRIDE]
    __shared__ int s_rel[BM], s_rt[BM], s_ent[BM], s_trig[BM];

    const int g   = blockIdx.z;
    const int m0  = blockIdx.x * BM;
    const int cnt = g ? (N_ARGS - d_gsplit) : d_gsplit;
    if (m0 >= cnt) return;

    const int tid = threadIdx.x;
    if (tid < BM) {
        int r = m0 + tid;
        if (r < cnt) {
            int a  = d_perm[g * N_ARGS + r];
            int rl = arg_rel[a];
            s_rel[tid]  = rl;
            s_rt[tid]   = rtype_ids[rl];
            s_ent[tid]  = arg_ent[a];
            s_trig[tid] = arg_trig[a];
        } else {
            s_rel[tid] = 0; s_rt[tid] = 0; s_ent[tid] = 0; s_trig[tid] = -1;
        }
    }
    __syncthreads();

    const int arow = tid >> 1;            // 128 rows, 2 threads/row
    const int acol = (tid & 1) * 16;      // 16 floats per thread
    const int brow = tid >> 3;            // 32 k-rows, 8 threads/row
    const int bcol = (tid & 7) * 32;      // 32 halves per thread
    const __half* Wg = d_Wh + (size_t)g * (ARG_DIM * ROLE_DIM);

    auto load_a = [&](int ks, float4* v) {
        const float* src;
        if (ks < 8)       src = rel   + (size_t)s_rel[arow] * REL_R   + ks * 32;
        else if (ks == 8) src = rtype + (size_t)s_rt[arow]  * RTYPE_DIM;
        else              src = ent   + (size_t)s_ent[arow] * ENT_DIM + (ks - 9) * 32;
        src += acol;
        v[0] = reinterpret_cast<const float4*>(src)[0];
        v[1] = reinterpret_cast<const float4*>(src)[1];
        v[2] = reinterpret_cast<const float4*>(src)[2];
        v[3] = reinterpret_cast<const float4*>(src)[3];
    };
    auto store_a = [&](int buf, const float4* v) {
        __half2 h[8];
        #pragma unroll
        for (int i = 0; i < 4; i++) {
            h[2 * i]     = __floats2half2_rn(v[i].x, v[i].y);
            h[2 * i + 1] = __floats2half2_rn(v[i].z, v[i].w);
        }
        uint4 u0, u1;
        u0.x = *reinterpret_cast<unsigned*>(&h[0]); u0.y = *reinterpret_cast<unsigned*>(&h[1]);
        u0.z = *reinterpret_cast<unsigned*>(&h[2]); u0.w = *reinterpret_cast<unsigned*>(&h[3]);
        u1.x = *reinterpret_cast<unsigned*>(&h[4]); u1.y = *reinterpret_cast<unsigned*>(&h[5]);
        u1.z = *reinterpret_cast<unsigned*>(&h[6]); u1.w = *reinterpret_cast<unsigned*>(&h[7]);
        __half* base = As + buf * (BM * AS_STRIDE) + arow * AS_STRIDE + acol;
        *reinterpret_cast<uint4*>(base)     = u0;
        *reinterpret_cast<uint4*>(base + 8) = u1;
    };
    auto load_b = [&](int ks, int stg) {
        const __half* src = Wg + (size_t)(ks * BK + brow) * ROLE_DIM + bcol;
        unsigned dst = (unsigned)__cvta_generic_to_shared(
            &Bs[stg * (BK * BS_STRIDE) + brow * BS_STRIDE + bcol]);
        unsigned long long gsrc = (unsigned long long)__cvta_generic_to_global(src);
        asm volatile("cp.async.cg.shared.global [%0], [%1], 16;" :: "r"(dst), "l"(gsrc) : "memory");
        asm volatile("cp.async.cg.shared.global [%0], [%1], 16;" :: "r"(dst + 16), "l"(gsrc + 16) : "memory");
        asm volatile("cp.async.cg.shared.global [%0], [%1], 16;" :: "r"(dst + 32), "l"(gsrc + 32) : "memory");
        asm volatile("cp.async.cg.shared.global [%0], [%1], 16;" :: "r"(dst + 48), "l"(gsrc + 48) : "memory");
        asm volatile("cp.async.commit_group;" ::: "memory");
    };

    const int lane = tid & 31;
    const int wid  = tid >> 5;            // 0..7
    const int wm   = (wid & 1) * 64;      // warp M base (2 warps over M)
    const int wn   = (wid >> 1) * 64;     // warp N base (4 warps over N)

    float acc[4][8][4];
    #pragma unroll
    for (int i = 0; i < 4; i++)
        #pragma unroll
        for (int j = 0; j < 8; j++)
            #pragma unroll
            for (int q = 0; q < 4; q++) acc[i][j][q] = 0.f;

    auto mma_step = [&](const __half* Ab, const __half* Bb) {
        #pragma unroll
        for (int kk = 0; kk < 2; kk++) {
            unsigned a[4][4];
            #pragma unroll
            for (int mi = 0; mi < 4; mi++) {
                unsigned addr = (unsigned)__cvta_generic_to_shared(
                    Ab + (wm + mi * 16 + (lane & 15)) * AS_STRIDE + kk * 16 + (lane >> 4) * 8);
                asm volatile("ldmatrix.sync.aligned.m8n8.x4.shared.b16 {%0,%1,%2,%3}, [%4];"
                             : "=r"(a[mi][0]), "=r"(a[mi][1]), "=r"(a[mi][2]), "=r"(a[mi][3])
                             : "r"(addr));
            }
            #pragma unroll
            for (int nj = 0; nj < 4; nj++) {
                unsigned b[4];
                unsigned baddr = (unsigned)__cvta_generic_to_shared(
                    Bb + (kk * 16 + (lane & 15)) * BS_STRIDE + wn + nj * 16 + (lane >> 4) * 8);
                asm volatile("ldmatrix.sync.aligned.m8n8.x4.trans.shared.b16 {%0,%1,%2,%3}, [%4];"
                             : "=r"(b[0]), "=r"(b[1]), "=r"(b[2]), "=r"(b[3])
                             : "r"(baddr));
                #pragma unroll
                for (int mi = 0; mi < 4; mi++) {
                    asm volatile("mma.sync.aligned.m16n8k16.row.col.f32.f16.f16.f32 "
                                 "{%0,%1,%2,%3}, {%4,%5,%6,%7}, {%8,%9}, {%0,%1,%2,%3};"
                                 : "+f"(acc[mi][2 * nj][0]), "+f"(acc[mi][2 * nj][1]),
                                   "+f"(acc[mi][2 * nj][2]), "+f"(acc[mi][2 * nj][3])
                                 : "r"(a[mi][0]), "r"(a[mi][1]), "r"(a[mi][2]), "r"(a[mi][3]),
                                   "r"(b[0]), "r"(b[1]));
                    asm volatile("mma.sync.aligned.m16n8k16.row.col.f32.f16.f16.f32 "
                                 "{%0,%1,%2,%3}, {%4,%5,%6,%7}, {%8,%9}, {%0,%1,%2,%3};"
                                 : "+f"(acc[mi][2 * nj + 1][0]), "+f"(acc[mi][2 * nj + 1][1]),
                                   "+f"(acc[mi][2 * nj + 1][2]), "+f"(acc[mi][2 * nj + 1][3])
                                 : "r"(a[mi][0]), "r"(a[mi][1]), "r"(a[mi][2]), "r"(a[mi][3]),
                                   "r"(b[2]), "r"(b[3]));
                }
            }
        }
    };

    // ---- software pipeline: A distance-2 register prefetch, B 3-stage cp.async ----
    float4 aC[4], aN[4];
    load_a(0, aC);                        // step 0 -> set C
    load_b(0, 0);
    load_b(1, 1);
    store_a(0, aC);
    load_a(1, aN);                        // step 1 -> set N (in flight)
    asm volatile("cp.async.wait_group 1;" ::: "memory");   // stage 0 ready
    __syncthreads();

    #pragma unroll 2
    for (int ks = 0; ks < NKSTEP; ks++) {
        mma_step(As + (ks & 1) * (BM * AS_STRIDE),
                 Bs + (ks % 3) * (BK * BS_STRIDE));
        __syncthreads();
        if (ks + 1 < NKSTEP) {
            if (ks & 1) store_a((ks + 1) & 1, aC);   // odd ks: step ks+1 in C
            else        store_a((ks + 1) & 1, aN);   // even ks: step ks+1 in N
        }
        if (ks + 2 < NKSTEP) {
            if (ks & 1) load_a(ks + 2, aN);
            else        load_a(ks + 2, aC);
            load_b(ks + 2, (ks + 2) % 3);
            asm volatile("cp.async.wait_group 1;" ::: "memory");  // stage ks+1 ready
        } else {
            asm volatile("cp.async.wait_group 0;" ::: "memory");
        }
        __syncthreads();
    }

    // -------- epilogue: staged segmented reduction (rows sorted by trigger) ----
    float* fb = reinterpret_cast<float*>(smem);
    #pragma unroll
    for (int q = 0; q < 2; q++) {
        __syncthreads();
        // 4 warps whose wn falls in this 128-col chunk stage their fragments
        if (((wid >> 1) >> 1) == q) {
            int colbase = ((wid >> 1) & 1) * 64;
            #pragma unroll
            for (int mi = 0; mi < 4; mi++) {
                int r0 = wm + mi * 16 + (lane >> 2);
                #pragma unroll
                for (int f = 0; f < 8; f++) {
                    int c = colbase + f * 8 + (lane & 3) * 2;
                    *reinterpret_cast<float2*>(&fb[r0 * EP_STRIDE + c]) =
                        make_float2(acc[mi][f][0], acc[mi][f][1]);
                    *reinterpret_cast<float2*>(&fb[(r0 + 8) * EP_STRIDE + c]) =
                        make_float2(acc[mi][f][2], acc[mi][f][3]);
                }
            }
        }
        __syncthreads();
        // 256 threads: 32 col-units (4 cols) x 8 row-windows (16 rows)
        int c4   = (tid & 31) * 4;
        int rbeg = (tid >> 5) * 16;
        float4 s = make_float4(0.f, 0.f, 0.f, 0.f);
        int cur = -2;
        #pragma unroll
        for (int r = rbeg; r < rbeg + 16; r++) {
            int t = s_trig[r];
            if (t != cur) {
                if (cur >= 0) {
                    float* p = out + (size_t)cur * OUT_DIM + ENT_DIM + q * 128 + c4;
                    asm volatile("red.global.add.v4.f32 [%0], {%1,%2,%3,%4};"
                                 :: "l"(p), "f"(s.x), "f"(s.y), "f"(s.z), "f"(s.w) : "memory");
                }
                s = make_float4(0.f, 0.f, 0.f, 0.f);
                cur = t;
            }
            float4 v = *reinterpret_cast<float4*>(&fb[r * EP_STRIDE + c4]);
            s.x += v.x; s.y += v.y; s.z += v.z; s.w += v.w;
        }
        if (cur >= 0) {
            float* p = out + (size_t)cur * OUT_DIM + ENT_DIM + q * 128 + c4;
            asm volatile("red.global.add.v4.f32 [%0], {%1,%2,%3,%4};"
                         :: "l"(p), "f"(s.x), "f"(s.y), "f"(s.z), "f"(s.w) : "memory");
        }
    }
}

extern "C" void kernel_launch(void* const* d_in, const int* in_sizes, int n_in,
                              void* d_out, int out_size) {
    const float* ent        = (const float*)d_in[0];
    const float* rel        = (const float*)d_in[1];
    const float* rtype      = (const float*)d_in[2];
    const float* W_in       = (const float*)d_in[3];
    const float* W_out      = (const float*)d_in[4];
    const int* rtype_ids    = (const int*)d_in[5];
    const int* trig_ent_id  = (const int*)d_in[6];
    const int* arg_trig     = (const int*)d_in[7];
    const int* arg_rel      = (const int*)d_in[8];
    const int* arg_ent      = (const int*)d_in[9];
    const int* arg_is_in    = (const int*)d_in[10];
    float* out = (float*)d_out;

    cudaFuncSetAttribute(gemm_kernel, cudaFuncAttributeMaxDynamicSharedMemorySize, SMEM_BYTES);

    zero_keys_kernel<<<(NKEY + 255) / 256, 256>>>();
    count_kernel<<<(N_ARGS + 255) / 256, 256>>>(arg_is_in, arg_trig);
    convw_kernel<<<(2 * ARG_DIM * ROLE_DIM + 255) / 256, 256>>>(W_in, W_out);
    scan_blocks_kernel<<<NSCANBLK, 1024>>>();
    scan_top_kernel<<<1, 128>>>();
    scan_add_kernel<<<NSCANBLK, 1024>>>();
    scatter_kernel<<<(N_ARGS + 255) / 256, 256>>>(arg_is_in, arg_trig);
    init_out_kernel<<<(N_TRIG + 3) / 4, dim3(136, 4)>>>(ent, trig_ent_id, out);

    dim3 grid((N_ARGS + BM - 1) / BM, 1, 2);
    gemm_kernel<<<grid, GTHREADS, SMEM_BYTES>>>(ent, rel, rtype, rtype_ids,
                                                arg_trig, arg_rel, arg_ent, out);
}

// round 9
// speedup vs baseline: 1.2549x; 1.2549x over previous
#include <cuda_runtime.h>
#include <cuda_fp16.h>

#define ENT_DIM   288
#define REL_R     256
#define RTYPE_DIM 32
#define ROLE_DIM  256
#define N_TRIG    50000
#define N_ARGS    250000
#define ARG_DIM   576
#define OUT_DIM   544
#define NKEY      (2 * N_TRIG)
#define NSCANBLK  ((NKEY + 1023) / 1024)     // 98

#define BM 128
#define BN 256
#define BK 32
#define NKSTEP 18              // 576 / 32
#define BSTAGE 3
#define AS_STRIDE 40           // 32 + 8 pad (conflict-free ldmatrix)
#define BS_STRIDE 264          // 256 + 8 pad
#define GTHREADS 512
#define EP_STRIDE 132          // epilogue fp32 stage stride (mult of 4)
// mainloop: A 2*128*40*2 = 20480 B, B 3*32*264*2 = 50688 B -> 71168
// epilogue: 128*132*4 = 67584 B
#define SMEM_BYTES 71168

// -------- device scratch (no allocation allowed) --------
__device__ __half d_Wh[2 * ARG_DIM * ROLE_DIM];   // [g][k][n], g=0 -> W_in
__device__ int    d_perm[2 * N_ARGS];
__device__ int    d_keycnt[NKEY];                  // zero-init; re-zeroed each run
__device__ int    d_keyoff[NKEY];
__device__ int    d_blocksum[NSCANBLK];
__device__ int    d_gsplit;                        // #args in group 0

// -------- prep kernels --------
__global__ void count_kernel(const int* __restrict__ arg_is_in,
                             const int* __restrict__ arg_trig) {
    int i = blockIdx.x * blockDim.x + threadIdx.x;
    if (i >= N_ARGS) return;
    int g = 1 - arg_is_in[i];
    atomicAdd(&d_keycnt[g * N_TRIG + arg_trig[i]], 1);
}

// block-local exclusive scan; re-zeros d_keycnt for the next graph replay
__global__ void scan_blocks_kernel() {
    __shared__ int wsum[32];
    int b = blockIdx.x, tid = threadIdx.x;
    int k = b * 1024 + tid;
    int c = (k < NKEY) ? d_keycnt[k] : 0;
    if (k < NKEY) d_keycnt[k] = 0;                 // restore invariant
    int v = c;
    #pragma unroll
    for (int d = 1; d < 32; d <<= 1) {
        int t = __shfl_up_sync(0xffffffffu, v, d);
        if ((tid & 31) >= d) v += t;
    }
    if ((tid & 31) == 31) wsum[tid >> 5] = v;
    __syncthreads();
    if (tid < 32) {
        int w = wsum[tid];
        #pragma unroll
        for (int d = 1; d < 32; d <<= 1) {
            int t = __shfl_up_sync(0xffffffffu, w, d);
            if (tid >= d) w += t;
        }
        wsum[tid] = w;
    }
    __syncthreads();
    int base = (tid >= 32) ? wsum[(tid >> 5) - 1] : 0;
    int incl = v + base;
    if (k < NKEY) d_keyoff[k] = incl - c;          // block-local exclusive
    if (tid == 1023) d_blocksum[b] = incl;
}

// merged: every block re-scans the 98 block sums, then adds its offset
__global__ void scan_finish_kernel() {
    __shared__ int s_off[NSCANBLK];
    __shared__ int wsum[4];
    int b = blockIdx.x, tid = threadIdx.x;
    if (tid < 128) {
        int c = (tid < NSCANBLK) ? d_blocksum[tid] : 0;
        int v = c;
        #pragma unroll
        for (int d = 1; d < 32; d <<= 1) {
            int t = __shfl_up_sync(0xffffffffu, v, d);
            if ((tid & 31) >= d) v += t;
        }
        if ((tid & 31) == 31) wsum[tid >> 5] = v;
    }
    __syncthreads();
    if (tid < 4) {
        int w = wsum[tid];
        #pragma unroll
        for (int d = 1; d < 4; d <<= 1) {
            int t = __shfl_up_sync(0x0000000fu, w, d);
            if (tid >= d) w += t;
        }
        wsum[tid] = w;
    }
    __syncthreads();
    if (tid < 128) {
        int c = (tid < NSCANBLK) ? d_blocksum[tid] : 0;
        int v = c;
        #pragma unroll
        for (int d = 1; d < 32; d <<= 1) {
            int t = __shfl_up_sync(0xffffffffu, v, d);
            if ((tid & 31) >= d) v += t;
        }
        int base = (tid >= 32) ? wsum[(tid >> 5) - 1] : 0;
        if (tid < NSCANBLK) s_off[tid] = v + base - c;
    }
    __syncthreads();
    int k = b * 1024 + tid;
    if (k < NKEY) {
        int off = d_keyoff[k] + s_off[b];
        d_keyoff[k] = off;
        if (k == N_TRIG) d_gsplit = off;
    }
}

__global__ void scatter_kernel(const int* __restrict__ arg_is_in,
                               const int* __restrict__ arg_trig) {
    int i = blockIdx.x * blockDim.x + threadIdx.x;
    if (i >= N_ARGS) return;
    int g = 1 - arg_is_in[i];
    int key = g * N_TRIG + arg_trig[i];
    int pos = atomicAdd(&d_keyoff[key], 1);
    int local = pos - (g ? d_gsplit : 0);
    d_perm[g * N_ARGS + local] = i;
}

__global__ void convw_kernel(const float* __restrict__ W_in,
                             const float* __restrict__ W_out) {
    int i = blockIdx.x * blockDim.x + threadIdx.x;
    if (i >= 2 * ARG_DIM * ROLE_DIM) return;
    float v = (i < ARG_DIM * ROLE_DIM) ? W_in[i] : W_out[i - ARG_DIM * ROLE_DIM];
    d_Wh[i] = __float2half(v);
}

// out[t][0:288] = ent_embeds[trig_ent_id[t]], out[t][288:544] = 0
__global__ void init_out_kernel(const float* __restrict__ ent,
                                const int* __restrict__ trig_ent_id,
                                float* __restrict__ out) {
    int t = blockIdx.x * 4 + threadIdx.y;
    int c = threadIdx.x;                  // 0..135 (float4 units)
    if (t >= N_TRIG) return;
    float4 v;
    if (c < ENT_DIM / 4) {
        v = reinterpret_cast<const float4*>(ent)[(size_t)trig_ent_id[t] * (ENT_DIM / 4) + c];
    } else {
        v = make_float4(0.f, 0.f, 0.f, 0.f);
    }
    reinterpret_cast<float4*>(out)[(size_t)t * (OUT_DIM / 4) + c] = v;
}

// -------- main GEMM: y = x @ W_g, x gathered/concatenated on the fly --------
__global__ void __launch_bounds__(GTHREADS, 1)
gemm_kernel(const float* __restrict__ ent,
            const float* __restrict__ rel,
            const float* __restrict__ rtype,
            const int*   __restrict__ rtype_ids,
            const int*   __restrict__ arg_trig,
            const int*   __restrict__ arg_rel,
            const int*   __restrict__ arg_ent,
            float*       __restrict__ out) {
    extern __shared__ __half smem[];
    __half* As = smem;                          // [2][BM][AS_STRIDE]
    __half* Bs = smem + 2 * BM * AS_STRIDE;     // [BSTAGE][BK][BS_STRIDE]
    __shared__ int s_rel[BM], s_rt[BM], s_ent[BM], s_trig[BM];

    const int g   = blockIdx.z;
    const int m0  = blockIdx.x * BM;
    const int cnt = g ? (N_ARGS - d_gsplit) : d_gsplit;
    if (m0 >= cnt) return;

    const int tid = threadIdx.x;
    if (tid < BM) {
        int r = m0 + tid;
        if (r < cnt) {
            int a  = d_perm[g * N_ARGS + r];
            int rl = arg_rel[a];
            s_rel[tid]  = rl;
            s_rt[tid]   = rtype_ids[rl];
            s_ent[tid]  = arg_ent[a];
            s_trig[tid] = arg_trig[a];
        } else {
            s_rel[tid] = 0; s_rt[tid] = 0; s_ent[tid] = 0; s_trig[tid] = -1;
        }
    }
    __syncthreads();

    const int arow = tid >> 2;            // 128 rows, 4 threads/row
    const int acol = (tid & 3) * 8;       // 8 floats per thread
    const int bk   = tid >> 4;            // 32 k-rows
    const int bn   = (tid & 15) * 16;     // 16 halves per thread
    const __half* Wg = d_Wh + (size_t)g * (ARG_DIM * ROLE_DIM);

    auto load_a = [&](int ks, float4& v0, float4& v1) {
        const float* src;
        if (ks < 8)       src = rel   + (size_t)s_rel[arow] * REL_R   + ks * 32;
        else if (ks == 8) src = rtype + (size_t)s_rt[arow]  * RTYPE_DIM;
        else              src = ent   + (size_t)s_ent[arow] * ENT_DIM + (ks - 9) * 32;
        v0 = *reinterpret_cast<const float4*>(src + acol);
        v1 = *reinterpret_cast<const float4*>(src + acol + 4);
    };
    auto store_a = [&](int buf, float4 v0, float4 v1) {
        __half2 h0 = __floats2half2_rn(v0.x, v0.y);
        __half2 h1 = __floats2half2_rn(v0.z, v0.w);
        __half2 h2 = __floats2half2_rn(v1.x, v1.y);
        __half2 h3 = __floats2half2_rn(v1.z, v1.w);
        uint4 u;
        u.x = *reinterpret_cast<unsigned*>(&h0);
        u.y = *reinterpret_cast<unsigned*>(&h1);
        u.z = *reinterpret_cast<unsigned*>(&h2);
        u.w = *reinterpret_cast<unsigned*>(&h3);
        *reinterpret_cast<uint4*>(&As[buf * (BM * AS_STRIDE) + arow * AS_STRIDE + acol]) = u;
    };
    auto load_b = [&](int ks, int stg) {
        const __half* src = Wg + (size_t)(ks * BK + bk) * ROLE_DIM + bn;
        unsigned dst = (unsigned)__cvta_generic_to_shared(
            &Bs[stg * (BK * BS_STRIDE) + bk * BS_STRIDE + bn]);
        unsigned long long gsrc = (unsigned long long)__cvta_generic_to_global(src);
        asm volatile("cp.async.cg.shared.global [%0], [%1], 16;" :: "r"(dst), "l"(gsrc) : "memory");
        asm volatile("cp.async.cg.shared.global [%0], [%1], 16;" :: "r"(dst + 16), "l"(gsrc + 16) : "memory");
        asm volatile("cp.async.commit_group;" ::: "memory");
    };

    const int lane = tid & 31;
    const int wid  = tid >> 5;
    const int wm   = (wid & 3) * 32;      // warp M base (4 warps over M)
    const int wn   = (wid >> 2) * 64;     // warp N base (4 warps over N)

    float acc[2][8][4];
    #pragma unroll
    for (int i = 0; i < 2; i++)
        #pragma unroll
        for (int j = 0; j < 8; j++)
            #pragma unroll
            for (int q = 0; q < 4; q++) acc[i][j][q] = 0.f;

    auto mma_step = [&](const __half* Ab, const __half* Bb) {
        #pragma unroll
        for (int kk = 0; kk < 2; kk++) {
            unsigned a[2][4];
            #pragma unroll
            for (int mi = 0; mi < 2; mi++) {
                unsigned addr = (unsigned)__cvta_generic_to_shared(
                    Ab + (wm + mi * 16 + (lane & 15)) * AS_STRIDE + kk * 16 + (lane >> 4) * 8);
                asm volatile("ldmatrix.sync.aligned.m8n8.x4.shared.b16 {%0,%1,%2,%3}, [%4];"
                             : "=r"(a[mi][0]), "=r"(a[mi][1]), "=r"(a[mi][2]), "=r"(a[mi][3])
                             : "r"(addr));
            }
            #pragma unroll
            for (int nj = 0; nj < 4; nj++) {
                unsigned b[4];
                unsigned baddr = (unsigned)__cvta_generic_to_shared(
                    Bb + (kk * 16 + (lane & 15)) * BS_STRIDE + wn + nj * 16 + (lane >> 4) * 8);
                asm volatile("ldmatrix.sync.aligned.m8n8.x4.trans.shared.b16 {%0,%1,%2,%3}, [%4];"
                             : "=r"(b[0]), "=r"(b[1]), "=r"(b[2]), "=r"(b[3])
                             : "r"(baddr));
                #pragma unroll
                for (int mi = 0; mi < 2; mi++) {
                    asm volatile("mma.sync.aligned.m16n8k16.row.col.f32.f16.f16.f32 "
                                 "{%0,%1,%2,%3}, {%4,%5,%6,%7}, {%8,%9}, {%0,%1,%2,%3};"
                                 : "+f"(acc[mi][2 * nj][0]), "+f"(acc[mi][2 * nj][1]),
                                   "+f"(acc[mi][2 * nj][2]), "+f"(acc[mi][2 * nj][3])
                                 : "r"(a[mi][0]), "r"(a[mi][1]), "r"(a[mi][2]), "r"(a[mi][3]),
                                   "r"(b[0]), "r"(b[1]));
                    asm volatile("mma.sync.aligned.m16n8k16.row.col.f32.f16.f16.f32 "
                                 "{%0,%1,%2,%3}, {%4,%5,%6,%7}, {%8,%9}, {%0,%1,%2,%3};"
                                 : "+f"(acc[mi][2 * nj + 1][0]), "+f"(acc[mi][2 * nj + 1][1]),
                                   "+f"(acc[mi][2 * nj + 1][2]), "+f"(acc[mi][2 * nj + 1][3])
                                 : "r"(a[mi][0]), "r"(a[mi][1]), "r"(a[mi][2]), "r"(a[mi][3]),
                                   "r"(b[2]), "r"(b[3]));
                }
            }
        }
    };

    // ---- software pipeline: A distance-2 register prefetch, B 3-stage cp.async ----
    float4 aC0, aC1, aN0, aN1;
    load_a(0, aC0, aC1);                  // step 0 -> set C
    load_b(0, 0);
    load_b(1, 1);
    store_a(0, aC0, aC1);
    load_a(1, aN0, aN1);                  // step 1 -> set N (in flight)
    asm volatile("cp.async.wait_group 1;" ::: "memory");   // stage 0 ready
    __syncthreads();

    #pragma unroll 2
    for (int ks = 0; ks < NKSTEP; ks++) {
        mma_step(As + (ks & 1) * (BM * AS_STRIDE),
                 Bs + (ks % 3) * (BK * BS_STRIDE));
        // NOTE: no barrier here. store_a below writes A-buffer (ks+1)&1 while any
        // laggard warp still in mma_step(ks) reads (ks)&1; cp.async below writes
        // B-stage (ks+2)%3 while mma reads ks%3 — disjoint. sync2 alone suffices.
        if (ks + 1 < NKSTEP) {
            if (ks & 1) store_a((ks + 1) & 1, aC0, aC1);   // odd ks: step ks+1 in C
            else        store_a((ks + 1) & 1, aN0, aN1);   // even ks: step ks+1 in N
        }
        if (ks + 2 < NKSTEP) {
            if (ks & 1) load_a(ks + 2, aN0, aN1);
            else        load_a(ks + 2, aC0, aC1);
            load_b(ks + 2, (ks + 2) % 3);
            asm volatile("cp.async.wait_group 1;" ::: "memory");  // stage ks+1 ready
        } else {
            asm volatile("cp.async.wait_group 0;" ::: "memory");
        }
        __syncthreads();
    }

    // -------- epilogue: staged segmented reduction (rows sorted by trigger) ----
    float* fb = reinterpret_cast<float*>(smem);
    #pragma unroll
    for (int q = 0; q < 2; q++) {
        __syncthreads();
        // 8 warps whose wn falls in this 128-col chunk stage their fragments
        if ((wid >> 3) == q) {
            int colbase = ((wid >> 2) & 1) * 64;
            #pragma unroll
            for (int mi = 0; mi < 2; mi++) {
                int r0 = wm + mi * 16 + (lane >> 2);
                #pragma unroll
                for (int f = 0; f < 8; f++) {
                    int c = colbase + f * 8 + (lane & 3) * 2;
                    *reinterpret_cast<float2*>(&fb[r0 * EP_STRIDE + c]) =
                        make_float2(acc[mi][f][0], acc[mi][f][1]);
                    *reinterpret_cast<float2*>(&fb[(r0 + 8) * EP_STRIDE + c]) =
                        make_float2(acc[mi][f][2], acc[mi][f][3]);
                }
            }
        }
        __syncthreads();
        // 512 threads: 32 col-units (4 cols) x 16 row-windows (8 rows)
        int c4   = (tid & 31) * 4;
        int rbeg = (tid >> 5) * 8;
        float4 s = make_float4(0.f, 0.f, 0.f, 0.f);
        int cur = -2;
        #pragma unroll
        for (int r = rbeg; r < rbeg + 8; r++) {
            int t = s_trig[r];
            if (t != cur) {
                if (cur >= 0) {
                    float* p = out + (size_t)cur * OUT_DIM + ENT_DIM + q * 128 + c4;
                    asm volatile("red.global.add.v4.f32 [%0], {%1,%2,%3,%4};"
                                 :: "l"(p), "f"(s.x), "f"(s.y), "f"(s.z), "f"(s.w) : "memory");
                }
                s = make_float4(0.f, 0.f, 0.f, 0.f);
                cur = t;
            }
            float4 v = *reinterpret_cast<float4*>(&fb[r * EP_STRIDE + c4]);
            s.x += v.x; s.y += v.y; s.z += v.z; s.w += v.w;
        }
        if (cur >= 0) {
            float* p = out + (size_t)cur * OUT_DIM + ENT_DIM + q * 128 + c4;
            asm volatile("red.global.add.v4.f32 [%0], {%1,%2,%3,%4};"
                         :: "l"(p), "f"(s.x), "f"(s.y), "f"(s.z), "f"(s.w) : "memory");
        }
    }
}

extern "C" void kernel_launch(void* const* d_in, const int* in_sizes, int n_in,
                              void* d_out, int out_size) {
    const float* ent        = (const float*)d_in[0];
    const float* rel        = (const float*)d_in[1];
    const float* rtype      = (const float*)d_in[2];
    const float* W_in       = (const float*)d_in[3];
    const float* W_out      = (const float*)d_in[4];
    const int* rtype_ids    = (const int*)d_in[5];
    const int* trig_ent_id  = (const int*)d_in[6];
    const int* arg_trig     = (const int*)d_in[7];
    const int* arg_rel      = (const int*)d_in[8];
    const int* arg_ent      = (const int*)d_in[9];
    const int* arg_is_in    = (const int*)d_in[10];
    float* out = (float*)d_out;

    cudaFuncSetAttribute(gemm_kernel, cudaFuncAttributeMaxDynamicSharedMemorySize, SMEM_BYTES);

    count_kernel<<<(N_ARGS + 255) / 256, 256>>>(arg_is_in, arg_trig);
    convw_kernel<<<(2 * ARG_DIM * ROLE_DIM + 255) / 256, 256>>>(W_in, W_out);
    scan_blocks_kernel<<<NSCANBLK, 1024>>>();
    scan_finish_kernel<<<NSCANBLK, 1024>>>();
    scatter_kernel<<<(N_ARGS + 255) / 256, 256>>>(arg_is_in, arg_trig);
    init_out_kernel<<<(N_TRIG + 3) / 4, dim3(136, 4)>>>(ent, trig_ent_id, out);

    dim3 grid((N_ARGS + BM - 1) / BM, 1, 2);
    gemm_kernel<<<grid, GTHREADS, SMEM_BYTES>>>(ent, rel, rtype, rtype_ids,
                                                arg_trig, arg_rel, arg_ent, out);
}